// round 16
// baseline (speedup 1.0000x reference)
#include <cuda_runtime.h>
#include <cstdint>
#include <math.h>

#define DIM      128
#define NPARAMS  8384
#define NT       256            // 8 warps

// Triangular 16-k-superblock-interleaved L layout.
// 16-row group g (rows 16g..16g+15): (g+1) superblocks per row, row stride
// GS[g] (all ≡ 16 mod 32, >= extent 16g+4(g>>1)+16), base GB[g] (≡ 0 mod 32).
// Superblock s of a row sits at off(s) = 16s + 4*(s>>1); within it,
// phys[4t+i] = logical[t+4i]  ->  thread tg's fragments for BOTH k-steps of
// the superblock (logical tg, tg+4, tg+8, tg+12) are one LDS.128 at 4*tg.
__constant__ int GB[8] = {0, 256, 1024, 2304, 3584, 5376, 7168, 9472};
__constant__ int GS[8] = {16, 48, 80, 80, 112, 112, 144, 144};

#define OFF_EPS  11776          // eps, tf32, superblock-interleaved, 128
#define OFF_LD   11904          // log-diag, 128
#define OFF_MEAN 12032
#define OFF_DIAG 12160
#define SMEM_FLOATS 12288       // 49152 B -> 4 CTAs/SM

// Work items: bit6 = pair (tiles (mt,nt),(mt+1,nt)), bits5:3 = mt, bits2:0 = nt.
__constant__ uint8_t TILE_TAB[8][6] = {
    {0x76, 0x40, 0xFF, 0xFF, 0xFF, 0xFF},
    {0x6D, 0x49, 0xFF, 0xFF, 0xFF, 0xFF},
    {0x64, 0x52, 0xFF, 0xFF, 0xFF, 0xFF},
    {0x74, 0x62, 0xFF, 0xFF, 0xFF, 0xFF},
    {0x5B, 0x3D, 0xFF, 0xFF, 0xFF, 0xFF},
    {0x6B, 0x72, 0xFF, 0xFF, 0xFF, 0xFF},
    {0x3F, 0x3B, 0x50, 0xFF, 0xFF, 0xFF},
    {0x59, 0x69, 0x39, 0x60, 0x70, 0xFF},
};

__device__ __forceinline__ int rowbase(int r) {
    const int g = r >> 4;
    return GB[g] + (r & 15) * GS[g];
}

__device__ __forceinline__ void mma_tf32(float* d, uint32_t a0, uint32_t a1,
                                         uint32_t a2, uint32_t a3,
                                         uint32_t b0, uint32_t b1) {
    asm volatile(
        "mma.sync.aligned.m16n8k8.row.col.f32.tf32.tf32.f32 "
        "{%0,%1,%2,%3}, {%4,%5,%6,%7}, {%8,%9}, {%0,%1,%2,%3};"
        : "+f"(d[0]), "+f"(d[1]), "+f"(d[2]), "+f"(d[3])
        : "r"(a0), "r"(a1), "r"(a2), "r"(a3), "r"(b0), "r"(b1));
}

__device__ __forceinline__ uint32_t to_tf32(float v) {
    uint32_t t;
    asm("cvt.rna.tf32.f32 %0, %1;" : "=r"(t) : "f"(v));
    return t;
}

// Process one 16-col superblock s of row r: load (fwd/reversed), transform,
// 4x4-transpose interleave, 4x STS.128.
__device__ __forceinline__ void sb_store(float* smf, const float* P,
                                         int r, int s, float rw) {
    float in[16];
    const int j0 = 16 * s;
    if (r < 64) {
        const float4* src = (const float4*)(P + 256 + 128 * r + j0);
        #pragma unroll
        for (int i = 0; i < 4; i++) {
            float4 v = src[i];
            in[4*i] = v.x; in[4*i+1] = v.y; in[4*i+2] = v.z; in[4*i+3] = v.w;
        }
    } else {
        // logical[x] = P[16511 - 128r - j0 - x]
        const float4* src = (const float4*)(P + 16496 - 128 * r - j0);
        #pragma unroll
        for (int i = 0; i < 4; i++) {
            float4 v = src[i];
            in[15-4*i] = v.x; in[14-4*i] = v.y; in[13-4*i] = v.z; in[12-4*i] = v.w;
        }
    }
    if (j0 + 15 < r) {
        #pragma unroll
        for (int e = 0; e < 16; e++) in[e] *= rw;
    } else {
        #pragma unroll
        for (int e = 0; e < 16; e++) {
            int j = j0 + e;
            float raw = in[e];
            if (j < r)       in[e] = raw * rw;
            else if (j == r) { smf[OFF_LD + r] = raw; in[e] = expf(raw); }
            else             in[e] = 0.0f;
        }
    }
    const int rb = rowbase(r) + j0 + 4 * (s >> 1);
    #pragma unroll
    for (int t = 0; t < 4; t++)
        *(uint4*)&smf[rb + 4*t] =
            make_uint4(to_tf32(in[t]),     to_tf32(in[t+4]),
                       to_tf32(in[t+8]),   to_tf32(in[t+12]));
}

// Old-layout off-diagonal store (direct float2 + xor4 mirror) for the
// second sub-tile of diag-lead pairs.
__device__ __forceinline__ void store_old_offdiag(char* SgB, const float d[2][4],
                                                  int m0, int n0, int gr, int tg) {
    const uint32_t rb = (uint32_t)(m0 + gr) * (DIM * 4);
    #pragma unroll
    for (int s = 0; s < 2; s++) {
        const uint32_t co = (uint32_t)(n0 + 8 * s + 2 * tg) * 4;
        *(float2*)(SgB + rb + co)               = make_float2(d[s][0], d[s][1]);
        *(float2*)(SgB + rb + 8 * DIM * 4 + co) = make_float2(d[s][2], d[s][3]);
    }
    const int odd  = gr & 1;
    const uint32_t ct = (uint32_t)(m0 + (gr & ~1)) * 4;
    #pragma unroll
    for (int s = 0; s < 2; s++) {
        float q0 = __shfl_xor_sync(0xffffffffu, d[s][0], 4);
        float q1 = __shfl_xor_sync(0xffffffffu, d[s][1], 4);
        float q2 = __shfl_xor_sync(0xffffffffu, d[s][2], 4);
        float q3 = __shfl_xor_sync(0xffffffffu, d[s][3], 4);
        const uint32_t rt = (uint32_t)(n0 + 8 * s + 2 * tg + odd) * (DIM * 4);
        float2 w0 = odd ? make_float2(q1, d[s][1]) : make_float2(d[s][0], q0);
        float2 w1 = odd ? make_float2(q3, d[s][3]) : make_float2(d[s][2], q2);
        *(float2*)(SgB + rt + ct)      = w0;
        *(float2*)(SgB + rt + ct + 32) = w1;
    }
}

// Permuted-layout store: 2x STG.128 direct + 8x scalar mirror.
__device__ __forceinline__ void store_perm(char* SgB, const float d[2][4],
                                           int m0, int n0, int gr, int tg) {
    const uint32_t co = (uint32_t)(n0 + 4 * tg) * 4;
    *(float4*)(SgB + (uint32_t)(m0 + gr) * (DIM * 4) + co) =
        make_float4(d[0][0], d[0][1], d[1][0], d[1][1]);
    *(float4*)(SgB + (uint32_t)(m0 + 8 + gr) * (DIM * 4) + co) =
        make_float4(d[0][2], d[0][3], d[1][2], d[1][3]);
    char* mb = SgB + (uint32_t)(n0 + 4 * tg) * (DIM * 4)
                   + (uint32_t)(m0 + gr) * 4;
    *(float*)(mb)             = d[0][0];
    *(float*)(mb + 512)       = d[0][1];
    *(float*)(mb + 1024)      = d[1][0];
    *(float*)(mb + 1536)      = d[1][1];
    *(float*)(mb + 32)        = d[0][2];
    *(float*)(mb + 512 + 32)  = d[0][3];
    *(float*)(mb + 1024 + 32) = d[1][2];
    *(float*)(mb + 1536 + 32) = d[1][3];
}

__global__ __launch_bounds__(NT, 4)
void fld_mma_kernel(const float* __restrict__ params,
                    const float* __restrict__ eps,
                    float* __restrict__ sample,
                    float* __restrict__ kl,
                    float* __restrict__ sigma)
{
    extern __shared__ float smf[];

    const int b   = blockIdx.x;
    const int tid = threadIdx.x;
    const int wid = tid >> 5;
    const int lid = tid & 31;
    const int gr  = lid >> 2;
    const int tg  = lid & 3;
    const float* P = params + (size_t)b * NPARAMS;

    // ---- phase 0: mean, eps (tf32, superblock-interleaved) ----
    if (tid < DIM) {
        smf[OFF_MEAN + tid] = P[tid];
        const int x = tid & 15;
        const int phys = (tid & ~15) + 4 * (x & 3) + (x >> 2);
        *(uint32_t*)&smf[OFF_EPS + phys] = to_tf32(eps[(size_t)b * DIM + tid]);
    }

    // ---- phase 1: coalesced triangular unpack (16-col superblocks) ----
    // rows >= 64: 4 rows/warp/iter (8 lanes each: s = lid&7)
    #pragma unroll
    for (int q = 0; q < 2; q++) {
        const int r = 64 + 32 * q + wid + 8 * (lid >> 3);
        const int s = lid & 7;
        if (s <= (r >> 4)) {
            const float rw = rsqrtf((float)(r + 1));
            sb_store(smf, P, r, s, rw);
        }
    }
    // rows < 64: 8 rows/warp (4 lanes each: s = lid&3), r = wid + 8*sub
    {
        const int r = wid + 8 * (lid >> 2);
        const int s = lid & 3;
        if (s <= (r >> 4)) {
            const float rw = rsqrtf((float)(r + 1));
            sb_store(smf, P, r, s, rw);
        }
    }
    __syncthreads();

    // ---- phase 2: m32n16 paired / single tiles; sample fused into diag ----
    char* SgB = (char*)(sigma + (size_t)b * DIM * DIM);

    for (int t = 0; t < 6; t++) {
        const uint32_t code = TILE_TAB[wid][t];
        if (code == 0xFF) break;
        const bool pair = (code & 0x40) != 0;
        const int mt0 = (code >> 3) & 7;
        const int nt  = code & 7;
        const int n0  = nt * 16;
        const int m0a = mt0 * 16;
        const bool alias = (mt0 == nt);
        const int nsb = nt + 1;               // superblocks (2 k-steps each)

        const int ar0 = rowbase(m0a + gr) + 4 * tg;
        const int ar1 = rowbase(m0a + 8 + gr) + 4 * tg;
        const int cr0 = rowbase(((m0a + 16) & 127) + gr) + 4 * tg;
        const int cr1 = rowbase(((m0a + 24) & 127) + gr) + 4 * tg;

        float d0[2][4], d1[2][4];
        #pragma unroll
        for (int s = 0; s < 2; s++)
            #pragma unroll
            for (int c = 0; c < 4; c++) { d0[s][c] = 0.0f; d1[s][c] = 0.0f; }

        if (alias) {
            // diag-lead: B aliases A; fused eps column for sample.
            float de[4] = {0.f, 0.f, 0.f, 0.f};
            for (int sb = 0; sb < nsb; sb++) {
                const int o = 16 * sb + 4 * (sb >> 1);
                uint4 A0 = *(const uint4*)&smf[ar0 + o];
                uint4 A1 = *(const uint4*)&smf[ar1 + o];
                uint4 E  = *(const uint4*)&smf[OFF_EPS + 16 * sb + 4 * tg];
                // k-step 2*sb
                mma_tf32(d0[0], A0.x, A1.x, A0.y, A1.y, A0.x, A0.y);
                mma_tf32(d0[1], A0.x, A1.x, A0.y, A1.y, A1.x, A1.y);
                mma_tf32(de,    A0.x, A1.x, A0.y, A1.y, E.x,  E.y);
                // k-step 2*sb+1
                mma_tf32(d0[0], A0.z, A1.z, A0.w, A1.w, A0.z, A0.w);
                mma_tf32(d0[1], A0.z, A1.z, A0.w, A1.w, A1.z, A1.w);
                mma_tf32(de,    A0.z, A1.z, A0.w, A1.w, E.z,  E.w);
                if (pair) {
                    uint4 C0 = *(const uint4*)&smf[cr0 + o];
                    uint4 C1 = *(const uint4*)&smf[cr1 + o];
                    mma_tf32(d1[0], C0.x, C1.x, C0.y, C1.y, A0.x, A0.y);
                    mma_tf32(d1[1], C0.x, C1.x, C0.y, C1.y, A1.x, A1.y);
                    mma_tf32(d1[0], C0.z, C1.z, C0.w, C1.w, A0.z, A0.w);
                    mma_tf32(d1[1], C0.z, C1.z, C0.w, C1.w, A1.z, A1.w);
                }
            }
            if (tg == 0) {
                sample[(size_t)b * DIM + m0a + gr] =
                    smf[OFF_MEAN + m0a + gr] + de[0];
                sample[(size_t)b * DIM + m0a + 8 + gr] =
                    smf[OFF_MEAN + m0a + 8 + gr] + de[2];
            }
            {
                const uint32_t rb = (uint32_t)(m0a + gr) * (DIM * 4);
                #pragma unroll
                for (int s = 0; s < 2; s++) {
                    const uint32_t co = (uint32_t)(n0 + 8 * s + 2 * tg) * 4;
                    *(float2*)(SgB + rb + co) =
                        make_float2(d0[s][0], d0[s][1]);
                    *(float2*)(SgB + rb + 8 * DIM * 4 + co) =
                        make_float2(d0[s][2], d0[s][3]);
                }
                if (2 * tg == (gr & ~1)) {
                    int c = gr & 1;
                    smf[OFF_DIAG + m0a + gr]     = d0[0][c];
                    smf[OFF_DIAG + m0a + gr + 8] = d0[1][2 + c];
                }
            }
            if (pair)
                store_old_offdiag(SgB, d1, m0a + 16, n0, gr, tg);
        } else {
            // permuted B rows -> thread owns 4 consecutive output columns
            const int pg  = ((gr >> 1) << 2) | (gr & 1);
            const int br0 = rowbase(n0 + pg) + 4 * tg;
            const int br1 = rowbase(n0 + pg + 2) + 4 * tg;
            for (int sb = 0; sb < nsb; sb++) {
                const int o = 16 * sb + 4 * (sb >> 1);
                uint4 A0 = *(const uint4*)&smf[ar0 + o];
                uint4 A1 = *(const uint4*)&smf[ar1 + o];
                uint4 B0 = *(const uint4*)&smf[br0 + o];
                uint4 B1 = *(const uint4*)&smf[br1 + o];
                mma_tf32(d0[0], A0.x, A1.x, A0.y, A1.y, B0.x, B0.y);
                mma_tf32(d0[1], A0.x, A1.x, A0.y, A1.y, B1.x, B1.y);
                mma_tf32(d0[0], A0.z, A1.z, A0.w, A1.w, B0.z, B0.w);
                mma_tf32(d0[1], A0.z, A1.z, A0.w, A1.w, B1.z, B1.w);
                if (pair) {
                    uint4 C0 = *(const uint4*)&smf[cr0 + o];
                    uint4 C1 = *(const uint4*)&smf[cr1 + o];
                    mma_tf32(d1[0], C0.x, C1.x, C0.y, C1.y, B0.x, B0.y);
                    mma_tf32(d1[1], C0.x, C1.x, C0.y, C1.y, B1.x, B1.y);
                    mma_tf32(d1[0], C0.z, C1.z, C0.w, C1.w, B0.z, B0.w);
                    mma_tf32(d1[1], C0.z, C1.z, C0.w, C1.w, B1.z, B1.w);
                }
            }
            store_perm(SgB, d0, m0a, n0, gr, tg);
            if (pair)
                store_perm(SgB, d1, m0a + 16, n0, gr, tg);
        }
    }
    __syncthreads();   // OFF_DIAG / OFF_LD complete

    // ---- phase 3: kl (warp 0) ----
    if (wid == 0) {
        float t = 0.0f;
        #pragma unroll
        for (int k = 0; k < 4; k++) {
            int rr = lid + 32 * k;
            float m = smf[OFF_MEAN + rr];
            t += smf[OFF_DIAG + rr] - 1.0f + m * m - 2.0f * smf[OFF_LD + rr];
        }
        #pragma unroll
        for (int o = 16; o > 0; o >>= 1)
            t += __shfl_down_sync(0xffffffffu, t, o);
        if (lid == 0) kl[b] = 0.5f * t;
    }
}

extern "C" void kernel_launch(void* const* d_in, const int* in_sizes, int n_in,
                              void* d_out, int out_size)
{
    const float* params = (const float*)d_in[0];
    const float* eps    = (const float*)d_in[1];
    const int B = in_sizes[0] / NPARAMS;

    float* out    = (float*)d_out;
    float* sample = out;                       // B * 128
    float* kl     = out + (size_t)B * DIM;     // B
    float* sigma  = kl + B;                    // B * 128 * 128

    const int smem = SMEM_FLOATS * sizeof(float);
    cudaFuncSetAttribute(fld_mma_kernel,
                         cudaFuncAttributeMaxDynamicSharedMemorySize, smem);
    fld_mma_kernel<<<B, NT, smem>>>(params, eps, sample, kl, sigma);
}

// round 17
// speedup vs baseline: 1.2001x; 1.2001x over previous
#include <cuda_runtime.h>
#include <cstdint>
#include <math.h>

#define DIM      128
#define NPARAMS  8384
#define NT       256            // 8 warps

// Triangular k-interleaved L layout (R14). 16-row group g stores 16(g+1)
// data cols, stride GS[g] (≡ 24 mod 32, >= data+16 so the +16 skew never
// overlaps the next row), base GB[g] (≡ 0 mod 32), +16 float skew on (r&4).
// Within each 8-col k-group, logical order [k0,k4,k1,k5,k2,k6,k3,k7]
// -> fragment pair (k+tg, k+tg+4) is one LDS.64 at phys offset 2*tg.
__constant__ int GB[8] = {0, 896, 1792, 3200, 4608, 6528, 8448, 10880};
__constant__ int GS[8] = {56, 56, 88, 88, 120, 120, 152, 152};

#define OFF_EPS  13312          // eps, tf32, k-interleaved, 128
#define OFF_LD   13440          // log-diag, 128
#define OFF_MEAN 13568
#define OFF_DIAG 13696
#define OFF_RW   13824          // rsqrt(r+1) table, 128
#define SMEM_FLOATS 13952       // 55808 B -> 4 CTAs/SM

// Work items: bit6 = pair (tiles (mt,nt),(mt+1,nt)), bits5:3 = mt, bits2:0 = nt.
__constant__ uint8_t TILE_TAB[8][6] = {
    {0x76, 0x40, 0xFF, 0xFF, 0xFF, 0xFF},
    {0x6D, 0x49, 0xFF, 0xFF, 0xFF, 0xFF},
    {0x64, 0x52, 0xFF, 0xFF, 0xFF, 0xFF},
    {0x74, 0x62, 0xFF, 0xFF, 0xFF, 0xFF},
    {0x5B, 0x3D, 0xFF, 0xFF, 0xFF, 0xFF},
    {0x6B, 0x72, 0xFF, 0xFF, 0xFF, 0xFF},
    {0x3F, 0x3B, 0x50, 0xFF, 0xFF, 0xFF},
    {0x59, 0x69, 0x39, 0x60, 0x70, 0xFF},
};

__device__ __forceinline__ int rowbase(int r) {
    const int g = r >> 4;
    return GB[g] + (r & 15) * GS[g] + ((r & 4) << 2);
}

__device__ __forceinline__ void mma_tf32(float* d, uint32_t a0, uint32_t a1,
                                         uint32_t a2, uint32_t a3,
                                         uint32_t b0, uint32_t b1) {
    asm volatile(
        "mma.sync.aligned.m16n8k8.row.col.f32.tf32.tf32.f32 "
        "{%0,%1,%2,%3}, {%4,%5,%6,%7}, {%8,%9}, {%0,%1,%2,%3};"
        : "+f"(d[0]), "+f"(d[1]), "+f"(d[2]), "+f"(d[3])
        : "r"(a0), "r"(a1), "r"(a2), "r"(a3), "r"(b0), "r"(b1));
}

__device__ __forceinline__ uint32_t to_tf32(float v) {
    uint32_t t;
    asm("cvt.rna.tf32.f32 %0, %1;" : "=r"(t) : "f"(v));
    return t;
}

// Transform 4 logical cols j0..j0+3 of row r (scale/exp/zero); save log-diag.
__device__ __forceinline__ float4 xform4(float* smf, int r, int j0,
                                         float rw, float4 v) {
    if (j0 + 3 < r) {
        v.x *= rw; v.y *= rw; v.z *= rw; v.w *= rw;
    } else {
        float vv[4] = {v.x, v.y, v.z, v.w};
        #pragma unroll
        for (int e = 0; e < 4; e++) {
            int j = j0 + e;
            float raw = vv[e];
            if (j < r)       vv[e] = raw * rw;
            else if (j == r) { smf[OFF_LD + r] = raw; vv[e] = expf(raw); }
            else             vv[e] = 0.0f;
        }
        v = make_float4(vv[0], vv[1], vv[2], vv[3]);
    }
    return v;
}

// Process one 8-col chunk of row r: transform + interleave-pack + 2x STS.128.
__device__ __forceinline__ void chunk_store(float* smf, const float* P,
                                            int r, int j0, float rw) {
    float4 lo = make_float4(0.f, 0.f, 0.f, 0.f);
    float4 hi = make_float4(0.f, 0.f, 0.f, 0.f);
    if (j0 <= r) {
        if (r < 64) {
            lo = *(const float4*)(P + 256 + 128 * r + j0);
            hi = *(const float4*)(P + 256 + 128 * r + j0 + 4);
        } else {
            float4 a = *(const float4*)(P + 16508 - 128 * r - j0);
            float4 b = *(const float4*)(P + 16504 - 128 * r - j0);
            lo = make_float4(a.w, a.z, a.y, a.x);
            hi = make_float4(b.w, b.z, b.y, b.x);
        }
        lo = xform4(smf, r, j0, rw, lo);
        hi = xform4(smf, r, j0 + 4, rw, hi);
    }
    const int rb = rowbase(r) + j0;
    *(uint4*)&smf[rb] = make_uint4(to_tf32(lo.x), to_tf32(hi.x),
                                   to_tf32(lo.y), to_tf32(hi.y));
    *(uint4*)&smf[rb + 4] = make_uint4(to_tf32(lo.z), to_tf32(hi.z),
                                       to_tf32(lo.w), to_tf32(hi.w));
}

// Old-layout off-diagonal store (direct float2 + xor4 mirror) for the
// second sub-tile of diag-lead pairs.
__device__ __forceinline__ void store_old_offdiag(char* SgB, const float d[2][4],
                                                  int m0, int n0, int gr, int tg) {
    const uint32_t rb = (uint32_t)(m0 + gr) * (DIM * 4);
    #pragma unroll
    for (int s = 0; s < 2; s++) {
        const uint32_t co = (uint32_t)(n0 + 8 * s + 2 * tg) * 4;
        *(float2*)(SgB + rb + co)               = make_float2(d[s][0], d[s][1]);
        *(float2*)(SgB + rb + 8 * DIM * 4 + co) = make_float2(d[s][2], d[s][3]);
    }
    const int odd  = gr & 1;
    const uint32_t ct = (uint32_t)(m0 + (gr & ~1)) * 4;
    #pragma unroll
    for (int s = 0; s < 2; s++) {
        float q0 = __shfl_xor_sync(0xffffffffu, d[s][0], 4);
        float q1 = __shfl_xor_sync(0xffffffffu, d[s][1], 4);
        float q2 = __shfl_xor_sync(0xffffffffu, d[s][2], 4);
        float q3 = __shfl_xor_sync(0xffffffffu, d[s][3], 4);
        const uint32_t rt = (uint32_t)(n0 + 8 * s + 2 * tg + odd) * (DIM * 4);
        float2 w0 = odd ? make_float2(q1, d[s][1]) : make_float2(d[s][0], q0);
        float2 w1 = odd ? make_float2(q3, d[s][3]) : make_float2(d[s][2], q2);
        *(float2*)(SgB + rt + ct)      = w0;
        *(float2*)(SgB + rt + ct + 32) = w1;
    }
}

// Permuted-layout store: 2x STG.128 direct + 8x scalar mirror.
__device__ __forceinline__ void store_perm(char* SgB, const float d[2][4],
                                           int m0, int n0, int gr, int tg) {
    const uint32_t co = (uint32_t)(n0 + 4 * tg) * 4;
    *(float4*)(SgB + (uint32_t)(m0 + gr) * (DIM * 4) + co) =
        make_float4(d[0][0], d[0][1], d[1][0], d[1][1]);
    *(float4*)(SgB + (uint32_t)(m0 + 8 + gr) * (DIM * 4) + co) =
        make_float4(d[0][2], d[0][3], d[1][2], d[1][3]);
    const uint32_t cm = (uint32_t)(m0 + gr) * 4;
    #pragma unroll
    for (int s = 0; s < 2; s++)
        #pragma unroll
        for (int e = 0; e < 2; e++) {
            const uint32_t rw = (uint32_t)(n0 + 4 * tg + 2 * s + e) * (DIM * 4);
            *(float*)(SgB + rw + cm)      = d[s][e];
            *(float*)(SgB + rw + cm + 32) = d[s][2 + e];
        }
}

__global__ __launch_bounds__(NT, 4)
void fld_mma_kernel(const float* __restrict__ params,
                    const float* __restrict__ eps,
                    float* __restrict__ sample,
                    float* __restrict__ kl,
                    float* __restrict__ sigma)
{
    extern __shared__ float smf[];

    const int b   = blockIdx.x;
    const int tid = threadIdx.x;
    const int wid = tid >> 5;
    const int lid = tid & 31;
    const int gr  = lid >> 2;
    const int tg  = lid & 3;
    const float* P = params + (size_t)b * NPARAMS;

    // ---- phase 0: mean, eps (tf32, k-interleaved), rsqrt table ----
    if (tid < DIM) {
        smf[OFF_MEAN + tid] = P[tid];
        smf[OFF_RW + tid]   = rsqrtf((float)(tid + 1));
        const int lo3 = tid & 7;
        const int phys = (tid & ~7) | ((lo3 < 4) ? (lo3 << 1) : (((lo3 - 4) << 1) | 1));
        *(uint32_t*)&smf[OFF_EPS + phys] = to_tf32(eps[(size_t)b * DIM + tid]);
    }
    __syncthreads();

    // ---- phase 1: coalesced triangular unpack (8-col chunks) ----
    #pragma unroll
    for (int q = 0; q < 4; q++) {
        const int r  = 64 + wid + 8 * q + 32 * (lid >> 4);
        const int j0 = (lid & 15) << 3;
        if (j0 < (r & ~15) + 16) {
            const float rw = smf[OFF_RW + r];
            chunk_store(smf, P, r, j0, rw);
        }
    }
    #pragma unroll
    for (int q = 0; q < 2; q++) {
        const int base = wid * 4 + (lid >> 3);
        const int r  = q ? (63 - base) : base;
        const int j0 = (lid & 7) << 3;
        if (j0 < (r & ~15) + 16) {
            const float rw = smf[OFF_RW + r];
            chunk_store(smf, P, r, j0, rw);
        }
    }
    __syncthreads();

    // ---- phase 2: m32n16 paired / single tiles; sample fused into diag ----
    char* SgB = (char*)(sigma + (size_t)b * DIM * DIM);

    for (int t = 0; t < 6; t++) {
        const uint32_t code = TILE_TAB[wid][t];
        if (code == 0xFF) break;
        const bool pair = (code & 0x40) != 0;
        const int mt0 = (code >> 3) & 7;
        const int nt  = code & 7;
        const int n0  = nt * 16;
        const int m0a = mt0 * 16;
        const bool alias = (mt0 == nt);
        const int ksteps = 2 * (nt + 1);

        const int ar0 = rowbase(m0a + gr) + 2 * tg;
        const int ar1 = rowbase(m0a + 8 + gr) + 2 * tg;
        const int cr0 = rowbase(((m0a + 16) & 127) + gr) + 2 * tg;
        const int cr1 = rowbase(((m0a + 24) & 127) + gr) + 2 * tg;

        float d0[2][4], d1[2][4];
        #pragma unroll
        for (int s = 0; s < 2; s++)
            #pragma unroll
            for (int c = 0; c < 4; c++) { d0[s][c] = 0.0f; d1[s][c] = 0.0f; }

        if (alias) {
            // diag-lead: B aliases A; fused eps column for sample.
            float de[4] = {0.f, 0.f, 0.f, 0.f};
            #pragma unroll 2
            for (int ks = 0; ks < ksteps; ks++) {
                const int k0 = ks * 8;
                uint2 A0 = *(const uint2*)&smf[ar0 + k0];   // (a0, a2)
                uint2 A1 = *(const uint2*)&smf[ar1 + k0];   // (a1, a3)
                mma_tf32(d0[0], A0.x, A1.x, A0.y, A1.y, A0.x, A0.y);
                mma_tf32(d0[1], A0.x, A1.x, A0.y, A1.y, A1.x, A1.y);
                uint2 E = make_uint2(0u, 0u);
                if (gr == 0)
                    E = *(const uint2*)&smf[OFF_EPS + k0 + 2 * tg];
                mma_tf32(de, A0.x, A1.x, A0.y, A1.y, E.x, E.y);
                if (pair) {
                    uint2 C0 = *(const uint2*)&smf[cr0 + k0];
                    uint2 C1 = *(const uint2*)&smf[cr1 + k0];
                    mma_tf32(d1[0], C0.x, C1.x, C0.y, C1.y, A0.x, A0.y);
                    mma_tf32(d1[1], C0.x, C1.x, C0.y, C1.y, A1.x, A1.y);
                }
            }
            if (tg == 0) {
                sample[(size_t)b * DIM + m0a + gr] =
                    smf[OFF_MEAN + m0a + gr] + de[0];
                sample[(size_t)b * DIM + m0a + 8 + gr] =
                    smf[OFF_MEAN + m0a + 8 + gr] + de[2];
            }
            {
                const uint32_t rb = (uint32_t)(m0a + gr) * (DIM * 4);
                #pragma unroll
                for (int s = 0; s < 2; s++) {
                    const uint32_t co = (uint32_t)(n0 + 8 * s + 2 * tg) * 4;
                    *(float2*)(SgB + rb + co) =
                        make_float2(d0[s][0], d0[s][1]);
                    *(float2*)(SgB + rb + 8 * DIM * 4 + co) =
                        make_float2(d0[s][2], d0[s][3]);
                }
                if (2 * tg == (gr & ~1)) {
                    int c = gr & 1;
                    smf[OFF_DIAG + m0a + gr]     = d0[0][c];
                    smf[OFF_DIAG + m0a + gr + 8] = d0[1][2 + c];
                }
            }
            if (pair)
                store_old_offdiag(SgB, d1, m0a + 16, n0, gr, tg);
        } else {
            // permuted B rows -> thread owns 4 consecutive output columns
            const int pg  = ((gr >> 1) << 2) | (gr & 1);
            const int br0 = rowbase(n0 + pg) + 2 * tg;
            const int br1 = rowbase(n0 + pg + 2) + 2 * tg;
            #pragma unroll 2
            for (int ks = 0; ks < ksteps; ks++) {
                const int k0 = ks * 8;
                uint2 A0 = *(const uint2*)&smf[ar0 + k0];
                uint2 A1 = *(const uint2*)&smf[ar1 + k0];
                uint2 B0 = *(const uint2*)&smf[br0 + k0];
                uint2 B1 = *(const uint2*)&smf[br1 + k0];
                mma_tf32(d0[0], A0.x, A1.x, A0.y, A1.y, B0.x, B0.y);
                mma_tf32(d0[1], A0.x, A1.x, A0.y, A1.y, B1.x, B1.y);
                if (pair) {
                    uint2 C0 = *(const uint2*)&smf[cr0 + k0];
                    uint2 C1 = *(const uint2*)&smf[cr1 + k0];
                    mma_tf32(d1[0], C0.x, C1.x, C0.y, C1.y, B0.x, B0.y);
                    mma_tf32(d1[1], C0.x, C1.x, C0.y, C1.y, B1.x, B1.y);
                }
            }
            store_perm(SgB, d0, m0a, n0, gr, tg);
            if (pair)
                store_perm(SgB, d1, m0a + 16, n0, gr, tg);
        }
    }
    __syncthreads();   // OFF_DIAG / OFF_LD complete

    // ---- phase 3: kl (warp 0) ----
    if (wid == 0) {
        float t = 0.0f;
        #pragma unroll
        for (int k = 0; k < 4; k++) {
            int rr = lid + 32 * k;
            float m = smf[OFF_MEAN + rr];
            t += smf[OFF_DIAG + rr] - 1.0f + m * m - 2.0f * smf[OFF_LD + rr];
        }
        #pragma unroll
        for (int o = 16; o > 0; o >>= 1)
            t += __shfl_down_sync(0xffffffffu, t, o);
        if (lid == 0) kl[b] = 0.5f * t;
    }
}

extern "C" void kernel_launch(void* const* d_in, const int* in_sizes, int n_in,
                              void* d_out, int out_size)
{
    const float* params = (const float*)d_in[0];
    const float* eps    = (const float*)d_in[1];
    const int B = in_sizes[0] / NPARAMS;

    float* out    = (float*)d_out;
    float* sample = out;                       // B * 128
    float* kl     = out + (size_t)B * DIM;     // B
    float* sigma  = kl + B;                    // B * 128 * 128

    const int smem = SMEM_FLOATS * sizeof(float);
    cudaFuncSetAttribute(fld_mma_kernel,
                         cudaFuncAttributeMaxDynamicSharedMemorySize, smem);
    fld_mma_kernel<<<B, NT, smem>>>(params, eps, sample, kl, sigma);
}